// round 2
// baseline (speedup 1.0000x reference)
#include <cuda_runtime.h>
#include <cstdint>

// Shapes: x[8,64,512,512] f32, W[64,64], b[64], seg_w[4,4] -> out[8,64,512,512]
#define Bb 8
#define Cc 64
#define Oo 64
#define HW 512
#define PLANE_F4 (HW*HW/4)      // 65536 float4 per (b,c) plane
#define BAND_F4  (128*HW/4)     // 16384 float4 per 128-row band
#define NITEM    4096           // 2048 pool + 2048 bcast items
#define GRID     592            // 4 CTAs/SM on 148 SMs -> guaranteed resident

// scratch (__device__ globals: allocation-free rule)
__device__ float g_pooled[Bb*Cc*16];    // [b][c][i*4+j]
__device__ float g_weighted[Bb*Oo*16];  // [b][o][i*4+j]
__device__ int   g_poolcnt[Bb];
__device__ int   g_flag[Bb];
__device__ int   g_ticket;

__global__ void init_kernel()
{
    if (threadIdx.x < Bb) { g_poolcnt[threadIdx.x] = 0; g_flag[threadIdx.x] = 0; }
    if (threadIdx.x == 31) g_ticket = 0;
}

// Item schedule (pos -> kind,batch,t):
//   [0,512)     : pool b0, pool b1
//   [512,3584)  : groups of 512: bcast b(g) (256) then pool b(g+2) (256), g=0..5
//   [3584,4096) : bcast b6, bcast b7
// Guarantees pool items of batch b precede bcast items of batch b in list order,
// so with all CTAs resident the flag spins always make progress.
__global__ __launch_bounds__(256) void fused_kernel(
    const float4* __restrict__ x,
    const float*  __restrict__ Wm,
    const float*  __restrict__ bias,
    const float*  __restrict__ segw,
    float4* __restrict__ out)
{
    __shared__ float ws[8];
    __shared__ int   s_pos;
    __shared__ int   s_last;

    const int tid  = threadIdx.x;
    const int warp = tid >> 5;
    const int jseg = (tid & 127) >> 5;   // column segment, loop-invariant

    for (;;) {
        if (tid == 0) s_pos = atomicAdd(&g_ticket, 1);
        __syncthreads();
        const int pos = s_pos;
        if (pos >= NITEM) return;
        __syncthreads();   // protect s_pos before next iteration's overwrite

        int kind, b, t;
        if (pos < 512)        { kind = 0; b = pos >> 8; t = pos & 255; }
        else if (pos < 3584)  { int g = (pos - 512) >> 9; int r = (pos - 512) & 511;
                                if (r < 256) { kind = 1; b = g;     t = r; }
                                else         { kind = 0; b = g + 2; t = r & 255; } }
        else                  { kind = 1; b = 6 + ((pos - 3584) >> 8); t = pos & 255; }

        if (kind == 0) {
            // ---- pool item: (b, c = t>>2, i = t&3): mean over 128x128 block cols
            const int c  = t >> 2, i = t & 3;
            const int bc = b * Cc + c;
            const float4* base = x + (size_t)bc * PLANE_F4 + (size_t)i * BAND_F4;

            float acc = 0.0f;
            #pragma unroll 8
            for (int idx = tid; idx < BAND_F4; idx += 256) {
                float4 v = __ldcs(&base[idx]);
                acc += (v.x + v.y) + (v.z + v.w);
            }
            #pragma unroll
            for (int off = 16; off; off >>= 1)
                acc += __shfl_xor_sync(0xffffffffu, acc, off);
            if ((tid & 31) == 0) ws[warp] = acc;
            __syncthreads();

            if (tid == 0) {
                const float inv = 1.0f / 16384.0f;
                float* dst = g_pooled + bc * 16 + i * 4;
                dst[0] = (ws[0] + ws[4]) * inv;
                dst[1] = (ws[1] + ws[5]) * inv;
                dst[2] = (ws[2] + ws[6]) * inv;
                dst[3] = (ws[3] + ws[7]) * inv;
                __threadfence();                       // release pooled values
                int old = atomicAdd(&g_poolcnt[b], 1);
                s_last = (old == Cc * 4 - 1);          // last arrival runs linear
            }
            __syncthreads();

            if (s_last) {
                // ---- tiny linear + seg scale for batch b: 1024 outputs
                #pragma unroll
                for (int k = 0; k < 4; k++) {
                    const int idx2 = tid + k * 256;
                    const int o = idx2 >> 4, ij = idx2 & 15;
                    const float* p  = g_pooled + (b * Cc) * 16 + ij;
                    const float* wr = Wm + o * Cc;
                    float a = bias[o];
                    #pragma unroll 16
                    for (int cc = 0; cc < Cc; cc++)
                        a = fmaf(__ldcg(&p[cc * 16]), wr[cc], a);
                    g_weighted[(b * Oo + o) * 16 + ij] = a * segw[ij];
                }
                __threadfence();                       // release weighted values
                __syncthreads();
                if (tid == 0) atomicExch(&g_flag[b], 1);
            }
        } else {
            // ---- bcast item: (b, o = t>>2, i = t&3): fill 128-row band
            const int o  = t >> 2, i = t & 3;
            const int bo = b * Oo + o;

            if (tid == 0) {
                while (atomicAdd(&g_flag[b], 0) == 0) __nanosleep(200);
                __threadfence();                       // acquire
            }
            __syncthreads();

            const float v = __ldcg(&g_weighted[bo * 16 + i * 4 + jseg]);
            const float4 f = make_float4(v, v, v, v);
            float4* base = out + (size_t)bo * PLANE_F4 + (size_t)i * BAND_F4;

            #pragma unroll 8
            for (int idx = tid; idx < BAND_F4; idx += 256)
                __stcs(&base[idx], f);
        }
        __syncthreads();   // ws / s_last safe for next iteration
    }
}

extern "C" void kernel_launch(void* const* d_in, const int* in_sizes, int n_in,
                              void* d_out, int out_size)
{
    const float4* x    = (const float4*)d_in[0];
    const float*  Wm   = (const float*)d_in[1];
    const float*  bias = (const float*)d_in[2];
    const float*  segw = (const float*)d_in[3];
    float4* out = (float4*)d_out;

    init_kernel<<<1, 32>>>();
    fused_kernel<<<GRID, 256>>>(x, Wm, bias, segw, out);
}